// round 1
// baseline (speedup 1.0000x reference)
#include <cuda_runtime.h>
#include <cuda_bf16.h>
#include <math.h>

// Problem constants (match reference)
#define D       32
#define HALF    16
#define DP1     33      // D+1
#define RF      68      // padded relation row floats (17 float4)
#define RF4     17      // float4 per relation row
#define MAX_NR  1024

#define TPB     64      // samples (=threads) per block

// Precomputed per-relation table: [c0..c15, s0..s15, w0..w31, c0h, s0h, cv, pad]
__device__ float4 g_relTab[MAX_NR * RF4];

// ---------------------------------------------------------------------------
// Prelude: build the per-relation table. NR=1000 rows, trivial cost.
// ---------------------------------------------------------------------------
__global__ void build_rel_tab(const float* __restrict__ boost,
                              const float* __restrict__ rot,
                              const float* __restrict__ trans,
                              int NR) {
    int r = blockIdx.x * blockDim.x + threadIdx.x;
    if (r >= NR) return;

    float outv[RF];
    const float* ro = rot + r * D;
    #pragma unroll
    for (int j = 0; j < HALF; ++j) {
        float s, c;
        sincosf(ro[j], &s, &c);
        outv[j]        = c;
        outv[HALF + j] = s;
    }

    // boost uses only element 0, clipped to [-2,2]
    float rap = fminf(fmaxf(boost[r * D], -2.0f), 2.0f);
    float c0 = coshf(rap);
    float s0 = sinhf(rap);

    // translation -> v = 0.1*trans (time comp 0); vn = sqrt(max(sum v^2,1e-6))
    const float* tr = trans + r * D;
    float v[D];
    float sq = 0.0f;
    #pragma unroll
    for (int j = 0; j < D; ++j) {
        v[j] = 0.1f * tr[j];
        sq = fmaf(v[j], v[j], sq);
    }
    float vn = sqrtf(fmaxf(sq, 1e-6f));
    float cv = coshf(vn);
    float svn = sinhf(vn) / vn;
    #pragma unroll
    for (int j = 0; j < D; ++j)
        outv[32 + j] = svn * v[j];

    outv[64] = c0;
    outv[65] = s0;
    outv[66] = cv;
    outv[67] = 0.0f;

    float4* dst = g_relTab + r * RF4;
    #pragma unroll
    for (int k = 0; k < RF4; ++k)
        dst[k] = make_float4(outv[4*k], outv[4*k+1], outv[4*k+2], outv[4*k+3]);
}

// ---------------------------------------------------------------------------
// Main scoring kernel. One sample per thread; SMEM-staged cooperative gathers.
// ---------------------------------------------------------------------------
__global__ __launch_bounds__(TPB) void score_kernel(
        const int*   __restrict__ heads,
        const int*   __restrict__ rels,
        const int*   __restrict__ tails,
        const float* __restrict__ ent,    // [NE,33]
        const float* __restrict__ bias,   // [NE,1]
        float*       __restrict__ out,
        int B) {

    __shared__ float4 s_r4[TPB * RF4];   // 17408 B
    __shared__ float  s_h [TPB * DP1];   //  8448 B
    __shared__ float  s_t [TPB * DP1];   //  8448 B
    __shared__ int    s_hi[TPB];
    __shared__ int    s_ri[TPB];
    __shared__ int    s_ti[TPB];

    const int tid  = threadIdx.x;
    const int base = blockIdx.x * TPB;
    int i = base + tid;
    bool active = (i < B);
    int iclamp = active ? i : (B - 1);

    // Coalesced index + bias loads
    int hi = heads[iclamp];
    int ri = rels [iclamp];
    int ti = tails[iclamp];
    s_hi[tid] = hi; s_ri[tid] = ri; s_ti[tid] = ti;
    float bh = bias[hi];
    float bt = bias[ti];
    __syncthreads();

    // Cooperative gather of h and t rows (33 floats each).
    // Linear element index e = row*33 + col keeps STS coalesced and each
    // warp-LDG touching ~1 row (2 cache lines).
    #pragma unroll 3
    for (int e = tid; e < TPB * DP1; e += TPB) {
        int r = e / DP1;
        int c = e - r * DP1;
        s_h[e] = __ldg(ent + (s_hi[r] * DP1 + c));
        s_t[e] = __ldg(ent + (s_ti[r] * DP1 + c));
    }
    // Cooperative gather of relation rows (17 float4 each) from the table.
    #pragma unroll 3
    for (int e = tid; e < TPB * RF4; e += TPB) {
        int r = e / RF4;
        int c = e - r * RF4;
        s_r4[e] = g_relTab[s_ri[r] * RF4 + c];
    }
    __syncthreads();

    // ---- Phase 2: per-thread compute (fully unrolled) ----
    const float*  h  = s_h  + tid * DP1;
    const float*  t  = s_t  + tid * DP1;
    const float4* rr = s_r4 + tid * RF4;   // float4-stride 17: conflict-free

    // Unpack c[16], s[16]
    float cs[32];
    #pragma unroll
    for (int k = 0; k < 8; ++k) {
        float4 v = rr[k];
        cs[4*k+0] = v.x; cs[4*k+1] = v.y; cs[4*k+2] = v.z; cs[4*k+3] = v.w;
    }

    float x0 = h[0];
    float rot[D];
    #pragma unroll
    for (int j = 0; j < HALF; ++j) {
        float a = h[1 + j];
        float b = h[1 + HALF + j];
        float c = cs[j];
        float s = cs[HALF + j];
        rot[j]        = c * a - s * b;
        rot[HALF + j] = s * a + c * b;
    }

    float4 misc = rr[16];        // (c0, s0, cv, pad)
    // boost: new spatial[0] = x0*s0 + rot[0]*c0
    rot[0] = x0 * misc.y + rot[0] * misc.x;
    float cv = misc.z;

    // res_sp = cv*rot + w ; accumulate sum(res^2) and dot(res, t_spatial)
    float ss2 = 0.0f, dot = 0.0f;
    #pragma unroll
    for (int k = 0; k < 8; ++k) {
        float4 wv = rr[8 + k];
        int j = 4 * k;
        float res;
        res = fmaf(cv, rot[j+0], wv.x); ss2 = fmaf(res, res, ss2); dot = fmaf(res, t[1+j+0], dot);
        res = fmaf(cv, rot[j+1], wv.y); ss2 = fmaf(res, res, ss2); dot = fmaf(res, t[1+j+1], dot);
        res = fmaf(cv, rot[j+2], wv.z); ss2 = fmaf(res, res, ss2); dot = fmaf(res, t[1+j+2], dot);
        res = fmaf(cv, rot[j+3], wv.w); ss2 = fmaf(res, res, ss2); dot = fmaf(res, t[1+j+3], dot);
    }

    float t0  = t[0];
    float ht0 = sqrtf(1.0f + ss2);          // _project time component
    float inner = dot - ht0 * t0;           // Lorentz inner(h_trans, t)
    float ic  = fmaxf(-inner, 1.0f + 1e-6f);
    float dd  = acoshf(ic);
    if (active)
        out[i] = fmaf(-dd, dd, bh + bt);
}

// ---------------------------------------------------------------------------
// Launch
// ---------------------------------------------------------------------------
extern "C" void kernel_launch(void* const* d_in, const int* in_sizes, int n_in,
                              void* d_out, int out_size) {
    const int*   heads = (const int*)  d_in[0];
    const int*   rels  = (const int*)  d_in[1];
    const int*   tails = (const int*)  d_in[2];
    const float* ent   = (const float*)d_in[3];  // [NE,33]
    const float* bw    = (const float*)d_in[4];  // [NR,32] boost
    const float* rw    = (const float*)d_in[5];  // [NR,32] rot
    const float* tw    = (const float*)d_in[6];  // [NR,32] trans
    const float* bias  = (const float*)d_in[7];  // [NE,1]
    float* out = (float*)d_out;

    int B  = in_sizes[0];
    int NR = in_sizes[4] / D;

    build_rel_tab<<<(NR + 127) / 128, 128>>>(bw, rw, tw, NR);
    score_kernel<<<(B + TPB - 1) / TPB, TPB>>>(heads, rels, tails, ent, bias, out, B);
}

// round 2
// speedup vs baseline: 1.7009x; 1.7009x over previous
#include <cuda_runtime.h>
#include <cuda_bf16.h>
#include <math.h>

#define D       32
#define HALF    16
#define DP1     33      // D+1
#define RF4     17      // float4 per relation row: c[16],s[16],w[32],(c0,s0,cv,pad)
#define MAX_NR  1024

#define TPB     128     // samples (=threads) per block

__device__ float4 g_relTab[MAX_NR * RF4];

// ---------------------------------------------------------------------------
// Prelude: per-relation table (NR=1000 rows, negligible cost).
// ---------------------------------------------------------------------------
__global__ void build_rel_tab(const float* __restrict__ boost,
                              const float* __restrict__ rot,
                              const float* __restrict__ trans,
                              int NR) {
    int r = blockIdx.x * blockDim.x + threadIdx.x;
    if (r >= NR) return;

    float outv[RF4 * 4];
    const float* ro = rot + r * D;
    #pragma unroll
    for (int j = 0; j < HALF; ++j) {
        float s, c;
        sincosf(ro[j], &s, &c);
        outv[j]        = c;
        outv[HALF + j] = s;
    }

    float rap = fminf(fmaxf(boost[r * D], -2.0f), 2.0f);
    float c0 = coshf(rap);
    float s0 = sinhf(rap);

    const float* tr = trans + r * D;
    float v[D];
    float sq = 0.0f;
    #pragma unroll
    for (int j = 0; j < D; ++j) {
        v[j] = 0.1f * tr[j];
        sq = fmaf(v[j], v[j], sq);
    }
    float vn = sqrtf(fmaxf(sq, 1e-6f));
    float cv = coshf(vn);
    float svn = sinhf(vn) / vn;
    #pragma unroll
    for (int j = 0; j < D; ++j)
        outv[32 + j] = svn * v[j];

    outv[64] = c0;
    outv[65] = s0;
    outv[66] = cv;
    outv[67] = 0.0f;

    float4* dst = g_relTab + r * RF4;
    #pragma unroll
    for (int k = 0; k < RF4; ++k)
        dst[k] = make_float4(outv[4*k], outv[4*k+1], outv[4*k+2], outv[4*k+3]);
}

// ---------------------------------------------------------------------------
// Main kernel: smem stages ONLY the entity rows (cooperative gather);
// relation rows are read per-thread through L1 (heavily reused, NR=1000).
// ---------------------------------------------------------------------------
__global__ __launch_bounds__(TPB) void score_kernel(
        const int*   __restrict__ heads,
        const int*   __restrict__ rels,
        const int*   __restrict__ tails,
        const float* __restrict__ ent,    // [NE,33]
        const float* __restrict__ bias,   // [NE,1]
        float*       __restrict__ out,
        int B) {

    __shared__ float s_h [TPB * DP1];   // 16896 B
    __shared__ float s_t [TPB * DP1];   // 16896 B
    __shared__ int   s_hi[TPB];
    __shared__ int   s_ti[TPB];

    const int tid = threadIdx.x;
    int i = blockIdx.x * TPB + tid;
    bool active = (i < B);
    int ic = active ? i : (B - 1);

    int hi = heads[ic];
    int ri = rels [ic];
    int ti = tails[ic];
    s_hi[tid] = hi;
    s_ti[tid] = ti;
    float bh = __ldcg(bias + hi);
    float bt = __ldcg(bias + ti);
    __syncthreads();

    // Cooperative entity gather: linear element index keeps STS coalesced and
    // each warp-LDG confined to ~1 row (2 cache lines). L2-only (.cg) so the
    // streaming entity table doesn't evict the hot relation table from L1.
    #pragma unroll
    for (int it = 0; it < DP1; ++it) {
        int e = tid + it * TPB;
        int r = e / DP1;
        int c = e - r * DP1;
        s_h[e] = __ldcg(ent + (s_hi[r] * DP1 + c));
        s_t[e] = __ldcg(ent + (s_ti[r] * DP1 + c));
    }
    __syncthreads();

    // ---- Per-thread compute, fused (no rot[] array; low reg pressure) ----
    const float*  h  = s_h + tid * DP1;
    const float*  t  = s_t + tid * DP1;
    const float4* rr = g_relTab + ri * RF4;   // L1-resident

    float4 m  = __ldg(rr + 16);   // (c0, s0, cv, pad)
    float  cv = m.z;
    float  x0 = h[0];

    float ss2 = 0.0f, dot = 0.0f;
    #pragma unroll
    for (int k = 0; k < 4; ++k) {
        float4 c4 = __ldg(rr + k);        // cos  j=4k..4k+3
        float4 s4 = __ldg(rr + 4 + k);    // sin
        float4 wl = __ldg(rr + 8 + k);    // w    j
        float4 wh = __ldg(rr + 12 + k);   // w    j+16
        #pragma unroll
        for (int q = 0; q < 4; ++q) {
            int j = 4 * k + q;
            float a = h[1 + j];
            float b = h[1 + HALF + j];
            float c = (q == 0) ? c4.x : (q == 1) ? c4.y : (q == 2) ? c4.z : c4.w;
            float s = (q == 0) ? s4.x : (q == 1) ? s4.y : (q == 2) ? s4.z : s4.w;
            float w1 = (q == 0) ? wl.x : (q == 1) ? wl.y : (q == 2) ? wl.z : wl.w;
            float w2 = (q == 0) ? wh.x : (q == 1) ? wh.y : (q == 2) ? wh.z : wh.w;

            float r1 = c * a - s * b;            // rotated[j]
            float r2 = s * a + c * b;            // rotated[j+16]
            if (j == 0)                          // boost mixes time into x1
                r1 = fmaf(x0, m.y, r1 * m.x);

            float res1 = fmaf(cv, r1, w1);
            float res2 = fmaf(cv, r2, w2);
            ss2 = fmaf(res1, res1, ss2);
            ss2 = fmaf(res2, res2, ss2);
            dot = fmaf(res1, t[1 + j], dot);
            dot = fmaf(res2, t[1 + HALF + j], dot);
        }
    }

    float t0    = t[0];
    float ht0   = sqrtf(1.0f + ss2);       // _project time component
    float inner = dot - ht0 * t0;
    float icl   = fmaxf(-inner, 1.0f + 1e-6f);
    float dd    = acoshf(icl);
    if (active)
        out[i] = fmaf(-dd, dd, bh + bt);
}

// ---------------------------------------------------------------------------
extern "C" void kernel_launch(void* const* d_in, const int* in_sizes, int n_in,
                              void* d_out, int out_size) {
    const int*   heads = (const int*)  d_in[0];
    const int*   rels  = (const int*)  d_in[1];
    const int*   tails = (const int*)  d_in[2];
    const float* ent   = (const float*)d_in[3];
    const float* bw    = (const float*)d_in[4];
    const float* rw    = (const float*)d_in[5];
    const float* tw    = (const float*)d_in[6];
    const float* bias  = (const float*)d_in[7];
    float* out = (float*)d_out;

    int B  = in_sizes[0];
    int NR = in_sizes[4] / D;

    build_rel_tab<<<(NR + 127) / 128, 128>>>(bw, rw, tw, NR);
    score_kernel<<<(B + TPB - 1) / TPB, TPB>>>(heads, rels, tails, ent, bias, out, B);
}

// round 3
// speedup vs baseline: 3.9118x; 2.2998x over previous
#include <cuda_runtime.h>
#include <cuda_bf16.h>
#include <math.h>

#define D       32
#define HALF    16
#define DP1     33      // D+1
#define RF      68      // relation row floats: c[16],s[16],w[32],(c0,s0,cv,pad)
#define MAX_NR  1024

#define TPB     256

__device__ float g_relTab[MAX_NR * RF];

// ---------------------------------------------------------------------------
// Prelude: per-relation table (NR=1000 rows, negligible cost).
// ---------------------------------------------------------------------------
__global__ void build_rel_tab(const float* __restrict__ boost,
                              const float* __restrict__ rot,
                              const float* __restrict__ trans,
                              int NR) {
    int r = blockIdx.x * blockDim.x + threadIdx.x;
    if (r >= NR) return;

    float* dst = g_relTab + r * RF;
    const float* ro = rot + r * D;
    #pragma unroll
    for (int j = 0; j < HALF; ++j) {
        float s, c;
        sincosf(ro[j], &s, &c);
        dst[j]        = c;
        dst[HALF + j] = s;
    }

    float rap = fminf(fmaxf(boost[r * D], -2.0f), 2.0f);
    float c0 = coshf(rap);
    float s0 = sinhf(rap);

    const float* tr = trans + r * D;
    float v[D];
    float sq = 0.0f;
    #pragma unroll
    for (int j = 0; j < D; ++j) {
        v[j] = 0.1f * tr[j];
        sq = fmaf(v[j], v[j], sq);
    }
    float vn = sqrtf(fmaxf(sq, 1e-6f));
    float cv = coshf(vn);
    float svn = sinhf(vn) / vn;
    #pragma unroll
    for (int j = 0; j < D; ++j)
        dst[32 + j] = svn * v[j];

    dst[64] = c0;
    dst[65] = s0;
    dst[66] = cv;
    dst[67] = 0.0f;
}

// ---------------------------------------------------------------------------
// Warp-cooperative kernel: lane j owns dimension j; 32 samples per warp.
// No shared memory, no block syncs; coalesced row loads; shfl reductions.
// ---------------------------------------------------------------------------
__global__ __launch_bounds__(TPB) void score_warp(
        const int*   __restrict__ heads,
        const int*   __restrict__ rels,
        const int*   __restrict__ tails,
        const float* __restrict__ ent,    // [NE,33]
        const float* __restrict__ bias,   // [NE,1]
        float*       __restrict__ out,
        int B) {

    const unsigned FULL = 0xFFFFFFFFu;
    const int lane = threadIdx.x & 31;
    const int wid  = (blockIdx.x * TPB + threadIdx.x) >> 5;
    const int i    = wid * 32 + lane;        // this lane's own sample
    const int ic   = min(i, B - 1);

    // Coalesced per-lane loads of 32 samples' indices + own-sample bias.
    const int hi_v = heads[ic];
    const int ri_v = rels [ic];
    const int ti_v = tails[ic];
    const float bsum = __ldcg(bias + hi_v) + __ldcg(bias + ti_v);

    const float sgn = (lane < HALF) ? -1.0f : 1.0f;   // rotation sign per half
    const int   cj  = lane & (HALF - 1);

    float result = 0.0f;

    // Prefetch sample 0's rows (1 float/lane + broadcast time components).
    {
        // nothing; handled below via rolling prefetch registers
    }
    int h0i = __shfl_sync(FULL, hi_v, 0);
    int t0i = __shfl_sync(FULL, ti_v, 0);
    const float* hr0 = ent + h0i * DP1;
    const float* tr0 = ent + t0i * DP1;
    float hsp = __ldcg(hr0 + 1 + lane);
    float h0  = __ldcg(hr0);
    float tsp = __ldcg(tr0 + 1 + lane);
    float t0  = __ldcg(tr0);

    #pragma unroll 4
    for (int s = 0; s < 32; ++s) {
        // Prefetch sample s+1 while computing s.
        float nhsp = 0.f, nh0 = 0.f, ntsp = 0.f, nt0 = 0.f;
        if (s < 31) {
            int nh = __shfl_sync(FULL, hi_v, s + 1);
            int nt = __shfl_sync(FULL, ti_v, s + 1);
            const float* nhr = ent + nh * DP1;
            const float* ntr = ent + nt * DP1;
            nhsp = __ldcg(nhr + 1 + lane);
            nh0  = __ldcg(nhr);
            ntsp = __ldcg(ntr + 1 + lane);
            nt0  = __ldcg(ntr);
        }

        const int ri = __shfl_sync(FULL, ri_v, s);
        const float* R = g_relTab + ri * RF;
        float c  = __ldg(R + cj);             // cos[j]   (both halves share)
        float sn = __ldg(R + HALF + cj);      // sin[j]
        float w  = __ldg(R + 32 + lane);      // sinh(vn)/vn * v[lane]
        float4 m = *(const float4*)(R + 64);  // (c0, s0, cv, pad) 16B-aligned

        // Rotation: lane<16: c*a - s*b ; lane>=16: s*a + c*b  (partner = lane^16)
        float p = __shfl_xor_sync(FULL, hsp, HALF);
        float r = fmaf(sgn * sn, p, c * hsp);
        // Boost mixes time component into spatial dim 0 only.
        if (lane == 0) r = fmaf(h0, m.y, r * m.x);
        // Translation (precomputed): res = cosh(vn)*r + w
        float res = fmaf(m.z, r, w);

        float ss2 = res * res;
        float dt  = res * tsp;
        #pragma unroll
        for (int off = HALF; off; off >>= 1) {
            ss2 += __shfl_xor_sync(FULL, ss2, off);
            dt  += __shfl_xor_sync(FULL, dt,  off);
        }

        float ht0   = sqrtf(1.0f + ss2);      // _project time component
        float inner = dt - ht0 * t0;          // all lanes have broadcast t0
        float icl   = fmaxf(-inner, 1.0f + 1e-6f);
        float dd    = acoshf(icl);
        if (lane == s) result = -dd * dd;     // lane s keeps sample s

        hsp = nhsp; h0 = nh0; tsp = ntsp; t0 = nt0;
    }

    if (i < B) out[i] = result + bsum;        // fully coalesced store
}

// ---------------------------------------------------------------------------
extern "C" void kernel_launch(void* const* d_in, const int* in_sizes, int n_in,
                              void* d_out, int out_size) {
    const int*   heads = (const int*)  d_in[0];
    const int*   rels  = (const int*)  d_in[1];
    const int*   tails = (const int*)  d_in[2];
    const float* ent   = (const float*)d_in[3];
    const float* bw    = (const float*)d_in[4];
    const float* rw    = (const float*)d_in[5];
    const float* tw    = (const float*)d_in[6];
    const float* bias  = (const float*)d_in[7];
    float* out = (float*)d_out;

    int B  = in_sizes[0];
    int NR = in_sizes[4] / D;

    build_rel_tab<<<(NR + 127) / 128, 128>>>(bw, rw, tw, NR);
    int nwarps = (B + 31) / 32;
    int grid   = (nwarps * 32 + TPB - 1) / TPB;
    score_warp<<<grid, TPB>>>(heads, rels, tails, ent, bias, out, B);
}

// round 4
// speedup vs baseline: 4.1150x; 1.0519x over previous
#include <cuda_runtime.h>
#include <cuda_bf16.h>
#include <math.h>

#define D       32
#define HALF    16
#define DP1     33      // D+1
#define RSTRIDE 96      // floats per relation row (384 B, keeps rows 128B-aligned)
#define MAX_NR  1024

#define TPB     256

// Layout per relation (128B-aligned rows):
//   [0..31]  : (c[j], s[j]) float2 pairs, j=0..15           (128 B)
//   [32..63] : (w[j], w[j+16]) float2 pairs, j=0..15        (128 B)
//   [64..67] : (c0, s0, cv, pad) float4
__device__ __align__(128) float g_relTab[MAX_NR * RSTRIDE];

// ---------------------------------------------------------------------------
// Prelude: per-relation table (NR=1000 rows, negligible cost).
// ---------------------------------------------------------------------------
__global__ void build_rel_tab(const float* __restrict__ boost,
                              const float* __restrict__ rot,
                              const float* __restrict__ trans,
                              int NR) {
    int r = blockIdx.x * blockDim.x + threadIdx.x;
    if (r >= NR) return;

    float* dst = g_relTab + r * RSTRIDE;
    const float* ro = rot + r * D;
    #pragma unroll
    for (int j = 0; j < HALF; ++j) {
        float s, c;
        sincosf(ro[j], &s, &c);
        dst[2 * j]     = c;
        dst[2 * j + 1] = s;
    }

    float rap = fminf(fmaxf(boost[r * D], -2.0f), 2.0f);
    float c0 = coshf(rap);
    float s0 = sinhf(rap);

    const float* tr = trans + r * D;
    float v[D];
    float sq = 0.0f;
    #pragma unroll
    for (int j = 0; j < D; ++j) {
        v[j] = 0.1f * tr[j];
        sq = fmaf(v[j], v[j], sq);
    }
    float vn = sqrtf(fmaxf(sq, 1e-6f));
    float cv = coshf(vn);
    float svn = sinhf(vn) / vn;
    #pragma unroll
    for (int j = 0; j < HALF; ++j) {
        dst[32 + 2 * j]     = svn * v[j];
        dst[32 + 2 * j + 1] = svn * v[j + HALF];
    }

    dst[64] = c0;
    dst[65] = s0;
    dst[66] = cv;
    dst[67] = 0.0f;
}

// ---------------------------------------------------------------------------
// Half-warp cooperative kernel: lanes 0-15 process sample A, lanes 16-31
// sample B; lane l handles dims (l&15) and (l&15)+16 of its sample.
// Rotation pair is thread-local (no shfl); 4-level butterfly per half-warp;
// sqrt/acosh epilogue hoisted out of the loop (once per lane).
// ---------------------------------------------------------------------------
__global__ __launch_bounds__(TPB) void score_warp2(
        const int*   __restrict__ heads,
        const int*   __restrict__ rels,
        const int*   __restrict__ tails,
        const float* __restrict__ ent,    // [NE,33]
        const float* __restrict__ bias,   // [NE,1]
        float*       __restrict__ out,
        int B) {

    const unsigned FULL = 0xFFFFFFFFu;
    const int lane = threadIdx.x & 31;
    const int wid  = (blockIdx.x * TPB + threadIdx.x) >> 5;
    const int i    = wid * 32 + lane;        // this lane's own sample
    const int ic   = min(i, B - 1);

    const int l16  = lane & 15;
    const int gsel = lane & 16;              // 0 for half A, 16 for half B

    // Coalesced per-lane loads of the warp's 32 samples' indices + own bias.
    const int hi_v = heads[ic];
    const int ri_v = rels [ic];
    const int ti_v = tails[ic];
    const float bsum = __ldcg(bias + hi_v) + __ldcg(bias + ti_v);

    // Keeper registers for this lane's own sample.
    float kss2 = 0.0f, kdt = 0.0f, kt0 = 1.0f;

    // Prefetch iteration 0: halves A/B fetch samples 0 / 16.
    {
        int hI = __shfl_sync(FULL, hi_v, gsel);
        int tI = __shfl_sync(FULL, ti_v, gsel);
        // fallthrough into rolling registers below
        const float* hr = ent + hI * DP1;
        const float* tr = ent + tI * DP1;
        float ha = __ldcg(hr + 1 + l16);
        float hb = __ldcg(hr + 17 + l16);
        float h0 = __ldcg(hr);
        float ta = __ldcg(tr + 1 + l16);
        float tb = __ldcg(tr + 17 + l16);
        float t0 = __ldcg(tr);

        #pragma unroll 4
        for (int it = 0; it < 16; ++it) {
            // Prefetch next iteration's rows while computing this one.
            float nha = 0.f, nhb = 0.f, nh0 = 0.f;
            float nta = 0.f, ntb = 0.f, nt0 = 0.f;
            if (it < 15) {
                int srcl = (it + 1) | gsel;
                int nh = __shfl_sync(FULL, hi_v, srcl);
                int nt = __shfl_sync(FULL, ti_v, srcl);
                const float* nhr = ent + nh * DP1;
                const float* ntr = ent + nt * DP1;
                nha = __ldcg(nhr + 1 + l16);
                nhb = __ldcg(nhr + 17 + l16);
                nh0 = __ldcg(nhr);
                nta = __ldcg(ntr + 1 + l16);
                ntb = __ldcg(ntr + 17 + l16);
                nt0 = __ldcg(ntr);
            }

            int ri = __shfl_sync(FULL, ri_v, it | gsel);
            const float* R = g_relTab + ri * RSTRIDE;
            float2 cs = __ldg((const float2*)R + l16);          // (c, s)
            float2 wp = __ldg((const float2*)(R + 32) + l16);   // (w_j, w_j+16)
            float4 m  = __ldg((const float4*)(R + 64));         // (c0,s0,cv,_)

            // Rotation: pair (j, j+16) is thread-local.
            float r1 = cs.x * ha - cs.y * hb;              // rotated[j]
            float r2 = fmaf(cs.y, ha, cs.x * hb);          // rotated[j+16]
            if (l16 == 0)                                  // boost on dim 0
                r1 = fmaf(h0, m.y, r1 * m.x);
            float res1 = fmaf(m.z, r1, wp.x);
            float res2 = fmaf(m.z, r2, wp.y);

            float ss2 = fmaf(res1, res1, res2 * res2);
            float dt  = fmaf(res1, ta, res2 * tb);
            // Butterfly within each 16-lane half (both samples in parallel).
            #pragma unroll
            for (int off = 1; off < HALF; off <<= 1) {
                ss2 += __shfl_xor_sync(FULL, ss2, off);
                dt  += __shfl_xor_sync(FULL, dt,  off);
            }

            // Lane (it | gsel) owns sample it|gsel -> keep values.
            bool keep = (l16 == it);
            kss2 = keep ? ss2 : kss2;
            kdt  = keep ? dt  : kdt;
            kt0  = keep ? t0  : kt0;

            ha = nha; hb = nhb; h0 = nh0;
            ta = nta; tb = ntb; t0 = nt0;
        }
    }

    // Epilogue: once per lane, on its own sample.
    float ht0   = sqrtf(1.0f + kss2);          // _project time component
    float inner = kdt - ht0 * kt0;
    float icl   = fmaxf(-inner, 1.0f + 1e-6f);
    float dd    = acoshf(icl);
    if (i < B)
        out[i] = fmaf(-dd, dd, bsum);          // coalesced store
}

// ---------------------------------------------------------------------------
extern "C" void kernel_launch(void* const* d_in, const int* in_sizes, int n_in,
                              void* d_out, int out_size) {
    const int*   heads = (const int*)  d_in[0];
    const int*   rels  = (const int*)  d_in[1];
    const int*   tails = (const int*)  d_in[2];
    const float* ent   = (const float*)d_in[3];
    const float* bw    = (const float*)d_in[4];
    const float* rw    = (const float*)d_in[5];
    const float* tw    = (const float*)d_in[6];
    const float* bias  = (const float*)d_in[7];
    float* out = (float*)d_out;

    int B  = in_sizes[0];
    int NR = in_sizes[4] / D;

    build_rel_tab<<<(NR + 127) / 128, 128>>>(bw, rw, tw, NR);
    int nwarps = (B + 31) / 32;
    int grid   = (nwarps * 32 + TPB - 1) / TPB;
    score_warp2<<<grid, TPB>>>(heads, rels, tails, ent, bias, out, B);
}

// round 5
// speedup vs baseline: 5.2920x; 1.2860x over previous
#include <cuda_runtime.h>
#include <cuda_bf16.h>
#include <math.h>

#define D       32
#define HALF    16
#define DP1     33      // D+1
#define RSTRIDE 96      // floats per relation row (384 B -> rows 128B-aligned)
#define MAX_NR  1024

#define TPB     256

// Per-relation packed table (float4-addressable, 16B aligned):
//   R4[q]    = (c[q], s[q], c[q+8], s[q+8])          q = 0..7
//   R4[8+q]  = (w[q], w[q+16], w[q+8], w[q+24])      q = 0..7
//   R4[16]   = (c0, s0, cv, 0)
__device__ __align__(128) float g_relTab[MAX_NR * RSTRIDE];

// ---------------------------------------------------------------------------
// Prelude: warp-per-relation table build (1000 warps, ~2 us).
// ---------------------------------------------------------------------------
__global__ void build_rel_tab(const float* __restrict__ boost,
                              const float* __restrict__ rot,
                              const float* __restrict__ trans,
                              int NR) {
    const unsigned FULL = 0xFFFFFFFFu;
    int lane = threadIdx.x & 31;
    int r = (blockIdx.x * blockDim.x + threadIdx.x) >> 5;
    if (r >= NR) return;

    // v = 0.1*trans; vn = sqrt(max(sum v^2, 1e-6))
    float v  = 0.1f * trans[r * D + lane];
    float sq = v * v;
    #pragma unroll
    for (int off = 16; off; off >>= 1)
        sq += __shfl_xor_sync(FULL, sq, off);
    float vn  = sqrtf(fmaxf(sq, 1e-6f));
    float cv  = coshf(vn);
    float svn = sinhf(vn) / vn;
    float w   = svn * v;

    float rap = fminf(fmaxf(__shfl_sync(FULL, 10.0f * v, 0) * 0.0f +
                            boost[r * D], -2.0f), 2.0f);  // boost[r*D+0], all lanes
    float c0 = coshf(rap);
    float s0 = sinhf(rap);

    int q = lane & 7;
    float wq   = __shfl_sync(FULL, w, q);
    float wq16 = __shfl_sync(FULL, w, q + 16);
    float wq8  = __shfl_sync(FULL, w, q + 8);
    float wq24 = __shfl_sync(FULL, w, q + 24);

    float4* dst4 = (float4*)(g_relTab + r * RSTRIDE);
    if (lane < 8) {
        float s1, c1, s2, c2;
        sincosf(rot[r * D + q],     &s1, &c1);
        sincosf(rot[r * D + q + 8], &s2, &c2);
        dst4[q]     = make_float4(c1, s1, c2, s2);
        dst4[8 + q] = make_float4(wq, wq16, wq8, wq24);
    }
    if (lane == 0)
        dst4[16] = make_float4(c0, s0, cv, 0.0f);
}

// ---------------------------------------------------------------------------
// 8-lane-group kernel: 4 samples per iteration, 8 iterations per warp.
// Lane q in a group handles dims {q, q+8} and rotation partners {q+16, q+24}.
// Time components hoisted out of the loop; 3-level butterflies; epilogue
// (sqrt/acosh) once per lane on its own sample.
// ---------------------------------------------------------------------------
__global__ __launch_bounds__(TPB, 6) void score8(
        const int*   __restrict__ heads,
        const int*   __restrict__ rels,
        const int*   __restrict__ tails,
        const float* __restrict__ ent,    // [NE,33]
        const float* __restrict__ bias,   // [NE,1]
        float*       __restrict__ out,
        int B) {

    const unsigned FULL = 0xFFFFFFFFu;
    const int lane  = threadIdx.x & 31;
    const int wid   = (blockIdx.x * TPB + threadIdx.x) >> 5;
    const int i     = wid * 32 + lane;
    const int ic    = min(i, B - 1);
    const int q     = lane & 7;
    const int gbase = lane & 24;

    // Coalesced loads of the warp's 32 samples' indices; own-sample scalars.
    const int hi_v = heads[ic];
    const int ri_v = rels [ic];
    const int ti_v = tails[ic];
    const float bsum   = __ldcg(bias + hi_v) + __ldcg(bias + ti_v);
    const float h0_own = __ldcg(ent + hi_v * DP1);
    const float t0_own = __ldcg(ent + ti_v * DP1);

    float kss2 = 0.0f, kdt = 0.0f;

    #pragma unroll
    for (int it = 0; it < 8; ++it) {
        const int src = gbase | it;                    // sample this group does
        int   hs  = __shfl_sync(FULL, hi_v,   src);
        int   ts  = __shfl_sync(FULL, ti_v,   src);
        int   rs  = __shfl_sync(FULL, ri_v,   src);
        float h0s = __shfl_sync(FULL, h0_own, src);

        const float* hr = ent + hs * DP1;
        const float* tr = ent + ts * DP1;
        float a1  = __ldcg(hr + 1  + q);   // h_sp[q]
        float a2  = __ldcg(hr + 9  + q);   // h_sp[q+8]
        float b1  = __ldcg(hr + 17 + q);   // h_sp[q+16]
        float b2  = __ldcg(hr + 25 + q);   // h_sp[q+24]
        float ta1 = __ldcg(tr + 1  + q);
        float ta2 = __ldcg(tr + 9  + q);
        float tb1 = __ldcg(tr + 17 + q);
        float tb2 = __ldcg(tr + 25 + q);

        const float4* R4 = (const float4*)(g_relTab + rs * RSTRIDE);
        float4 cs = __ldg(R4 + q);         // c[q], s[q], c[q+8], s[q+8]
        float4 w  = __ldg(R4 + 8 + q);     // w[q], w[q+16], w[q+8], w[q+24]
        float4 m  = __ldg(R4 + 16);        // c0, s0, cv, -

        // Rotation (pairs are thread-local).
        float r1 = cs.x * a1 - cs.y * b1;            // rotated[q]
        float p1 = fmaf(cs.y, a1, cs.x * b1);        // rotated[q+16]
        float r2 = cs.z * a2 - cs.w * b2;            // rotated[q+8]
        float p2 = fmaf(cs.w, a2, cs.z * b2);        // rotated[q+24]
        if (q == 0)                                  // boost mixes h0 into dim 0
            r1 = fmaf(h0s, m.y, r1 * m.x);

        // Translation (precomputed): res = cv*rot + w
        float e1 = fmaf(m.z, r1, w.x);
        float f1 = fmaf(m.z, p1, w.y);
        float e2 = fmaf(m.z, r2, w.z);
        float f2 = fmaf(m.z, p2, w.w);

        float ss2 = fmaf(e1, e1, fmaf(f1, f1, fmaf(e2, e2, f2 * f2)));
        float dt  = fmaf(e1, ta1, fmaf(f1, tb1, fmaf(e2, ta2, f2 * tb2)));

        // 3-level butterfly within each 8-lane group (4 samples in parallel).
        #pragma unroll
        for (int off = 1; off < 8; off <<= 1) {
            ss2 += __shfl_xor_sync(FULL, ss2, off);
            dt  += __shfl_xor_sync(FULL, dt,  off);
        }

        // Lane (gbase|it) owns sample (gbase|it): keep when q == it.
        bool keep = (q == it);
        kss2 = keep ? ss2 : kss2;
        kdt  = keep ? dt  : kdt;
    }

    // Epilogue once per lane on its own sample.
    float ht0   = sqrtf(1.0f + kss2);        // _project time component
    float inner = kdt - ht0 * t0_own;
    float icl   = fmaxf(-inner, 1.0f + 1e-6f);
    float dd    = acoshf(icl);
    if (i < B)
        out[i] = fmaf(-dd, dd, bsum);        // coalesced store
}

// ---------------------------------------------------------------------------
extern "C" void kernel_launch(void* const* d_in, const int* in_sizes, int n_in,
                              void* d_out, int out_size) {
    const int*   heads = (const int*)  d_in[0];
    const int*   rels  = (const int*)  d_in[1];
    const int*   tails = (const int*)  d_in[2];
    const float* ent   = (const float*)d_in[3];
    const float* bw    = (const float*)d_in[4];
    const float* rw    = (const float*)d_in[5];
    const float* tw    = (const float*)d_in[6];
    const float* bias  = (const float*)d_in[7];
    float* out = (float*)d_out;

    int B  = in_sizes[0];
    int NR = in_sizes[4] / D;

    int bwarps = (NR * 32 + TPB - 1) / TPB;
    build_rel_tab<<<bwarps, TPB>>>(bw, rw, tw, NR);

    int nwarps = (B + 31) / 32;
    int grid   = (nwarps * 32 + TPB - 1) / TPB;
    score8<<<grid, TPB>>>(heads, rels, tails, ent, bias, out, B);
}

// round 6
// speedup vs baseline: 6.5621x; 1.2400x over previous
#include <cuda_runtime.h>
#include <cuda_bf16.h>
#include <math.h>

#define D        32
#define HALF     16
#define DP1      33       // D+1
#define RSTRIDE4 16       // float4s per relation row (256 B, 128B-aligned)
#define MAX_NR   1024
#define MAX_NE   1000000

#define TPB      256

// Per-relation table, one float4 per lane l16=0..15:
//   R4[l16] = (C, S, w1, w2) = (cv*c[l16], cv*s[l16], w[l16], w[l16+16])
__device__ __align__(256) float4 g_relTab[MAX_NR * RSTRIDE4];
// Per-relation boost scalars: (cv*s0, c0, w[0], 0)
__device__ float4 g_boost[MAX_NR];
// Per-entity packed (x0, bias)
__device__ float2 g_sc[MAX_NE];

// ---------------------------------------------------------------------------
// Prelude 1: warp-per-relation table build (1000 warps).
// ---------------------------------------------------------------------------
__global__ void build_rel_tab(const float* __restrict__ boost,
                              const float* __restrict__ rot,
                              const float* __restrict__ trans,
                              int NR) {
    const unsigned FULL = 0xFFFFFFFFu;
    int lane = threadIdx.x & 31;
    int r = (blockIdx.x * blockDim.x + threadIdx.x) >> 5;
    if (r >= NR) return;

    // v = 0.1*trans; vn = sqrt(max(sum v^2, 1e-6)); w = sinh(vn)/vn * v
    float v  = 0.1f * trans[r * D + lane];
    float sq = v * v;
    #pragma unroll
    for (int off = 16; off; off >>= 1)
        sq += __shfl_xor_sync(FULL, sq, off);
    float vn  = sqrtf(fmaxf(sq, 1e-6f));
    float cv  = coshf(vn);
    float svn = sinhf(vn) / vn;
    float w   = svn * v;

    float whi = __shfl_down_sync(FULL, w, 16);   // lane<16 gets w[lane+16]

    float s = 0.0f, c = 0.0f;
    float rv = (lane < HALF) ? rot[r * D + lane] : 0.0f;
    sincosf(rv, &s, &c);

    if (lane < HALF)
        g_relTab[r * RSTRIDE4 + lane] = make_float4(cv * c, cv * s, w, whi);

    if (lane == 0) {
        float rap = fminf(fmaxf(boost[r * D], -2.0f), 2.0f);
        float c0 = coshf(rap);
        float s0 = sinhf(rap);
        g_boost[r] = make_float4(cv * s0, c0, w /* = w[0] */, 0.0f);
    }
}

// ---------------------------------------------------------------------------
// Prelude 2: pack per-entity (x0, bias) into one float2 row.
// ---------------------------------------------------------------------------
__global__ void pack_sc(const float* __restrict__ ent,
                        const float* __restrict__ bias,
                        int NE) {
    int e = blockIdx.x * blockDim.x + threadIdx.x;
    if (e < NE)
        g_sc[e] = make_float2(__ldg(ent + e * DP1), __ldg(bias + e));
}

// ---------------------------------------------------------------------------
// Main: 16-lane groups, 2 samples/iter, 16 iters/warp.
// Lane l16 owns dims (l16, l16+16) of the group's sample. All relation math
// is one float4/lane; boost handled via shuffled per-sample scalars.
// ---------------------------------------------------------------------------
__global__ __launch_bounds__(TPB, 6) void score16(
        const int*   __restrict__ heads,
        const int*   __restrict__ rels,
        const int*   __restrict__ tails,
        const float* __restrict__ ent,    // [NE,33]
        float*       __restrict__ out,
        int B) {

    const unsigned FULL = 0xFFFFFFFFu;
    const int lane = threadIdx.x & 31;
    const int wid  = (blockIdx.x * TPB + threadIdx.x) >> 5;
    const int i    = wid * 32 + lane;
    const int ic   = min(i, B - 1);
    const int l16  = lane & 15;
    const int gsel = lane & 16;

    // Per-lane (own sample) scalars — coalesced idx loads, random float2/float4.
    const int hi_v = heads[ic];
    const int ri_v = rels [ic];
    const int ti_v = tails[ic];

    float2 sh = g_sc[hi_v];                 // (h0, bias_h)
    float2 st = g_sc[ti_v];                 // (t0, bias_t)
    float4 b4 = __ldg(&g_boost[ri_v]);      // (cv*s0, c0, w0, 0)
    const float bsum   = sh.y + st.y;
    const float t0_own = st.x;
    const float c0_own = b4.y;
    const float bterm  = fmaf(b4.x, sh.x, b4.z);   // cv*s0*h0 + w[0]

    float kss2 = 0.0f, kdt = 0.0f;

    #pragma unroll 4
    for (int it = 0; it < 16; ++it) {
        const int src = gsel | it;          // sample this half-warp processes
        int   hs   = __shfl_sync(FULL, hi_v,  src);
        int   ts   = __shfl_sync(FULL, ti_v,  src);
        int   rs   = __shfl_sync(FULL, ri_v,  src);
        float bts  = __shfl_sync(FULL, bterm, src);
        float c0s  = __shfl_sync(FULL, c0_own, src);

        const float* hr = ent + hs * DP1;
        const float* tr = ent + ts * DP1;
        float a  = __ldcg(hr + 1  + l16);   // h_sp[l16]
        float b  = __ldcg(hr + 17 + l16);   // h_sp[l16+16]
        float ta = __ldcg(tr + 1  + l16);
        float tb = __ldcg(tr + 17 + l16);

        float4 cw = __ldg(&g_relTab[rs * RSTRIDE4 + l16]);  // (C,S,w1,w2)

        float r1   = cw.x * a - cw.y * b;                   // cv * rotated[l16]
        float res1 = (l16 == 0) ? fmaf(c0s, r1, bts)        // boost + trans dim0
                                : (r1 + cw.z);
        float res2 = fmaf(cw.y, a, fmaf(cw.x, b, cw.w));    // cv*rot[l16+16]+w2

        float ss2 = fmaf(res1, res1, res2 * res2);
        float dt  = fmaf(res1, ta,   res2 * tb);

        // 4-level butterfly within each 16-lane half.
        #pragma unroll
        for (int off = 1; off < HALF; off <<= 1) {
            ss2 += __shfl_xor_sync(FULL, ss2, off);
            dt  += __shfl_xor_sync(FULL, dt,  off);
        }

        bool keep = (l16 == it);            // lane src owns sample src
        kss2 = keep ? ss2 : kss2;
        kdt  = keep ? dt  : kdt;
    }

    // Epilogue once per lane on its own sample.
    float ht0   = sqrtf(1.0f + kss2);       // _project time component
    float inner = kdt - ht0 * t0_own;
    float icl   = fmaxf(-inner, 1.0f + 1e-6f);
    float dd    = acoshf(icl);
    if (i < B)
        out[i] = fmaf(-dd, dd, bsum);       // coalesced store
}

// ---------------------------------------------------------------------------
extern "C" void kernel_launch(void* const* d_in, const int* in_sizes, int n_in,
                              void* d_out, int out_size) {
    const int*   heads = (const int*)  d_in[0];
    const int*   rels  = (const int*)  d_in[1];
    const int*   tails = (const int*)  d_in[2];
    const float* ent   = (const float*)d_in[3];
    const float* bw    = (const float*)d_in[4];
    const float* rw    = (const float*)d_in[5];
    const float* tw    = (const float*)d_in[6];
    const float* bias  = (const float*)d_in[7];
    float* out = (float*)d_out;

    int B  = in_sizes[0];
    int NR = in_sizes[4] / D;
    int NE = in_sizes[3] / DP1;

    build_rel_tab<<<(NR * 32 + TPB - 1) / TPB, TPB>>>(bw, rw, tw, NR);
    pack_sc<<<(NE + TPB - 1) / TPB, TPB>>>(ent, bias, NE);

    int nwarps = (B + 31) / 32;
    int grid   = (nwarps * 32 + TPB - 1) / TPB;
    score16<<<grid, TPB>>>(heads, rels, tails, ent, out, B);
}